// round 12
// baseline (speedup 1.0000x reference)
#include <cuda_runtime.h>
#include <cuda_fp16.h>

typedef unsigned long long ull;

// ---------------- device scratch (static) ----------------
__device__ float g_uw[256];                     // u/w projection vectors
__device__ unsigned g_bm[400 * 16];             // gso bitmap [i][word]
__device__ __align__(16) float g_E[256 * 3200]; // Ae,Ce,Be,De per graph
__device__ __align__(16) uint4 g_wfh[512];      // Wv hi fragments [16 (kk,ntp)][32 lanes]
__device__ __align__(16) uint4 g_wfl[512];      // Wv lo fragments

// ---------------- helpers ----------------
__device__ __forceinline__ unsigned f16pack(float hi, float lo) {
  unsigned r;
  asm("cvt.rn.f16x2.f32 %0, %1, %2;" : "=r"(r) : "f"(hi), "f"(lo));
  return r;
}
__device__ __forceinline__ float2 h2f(unsigned u) {
  __half2 h = *reinterpret_cast<__half2*>(&u);
  return __half22float2(h);
}
__device__ __forceinline__ unsigned s2u(const void* p) {
  return (unsigned)__cvta_generic_to_shared(p);
}
__device__ __forceinline__ void mma16816(float* c, const unsigned* a, unsigned b0, unsigned b1) {
  asm volatile(
      "mma.sync.aligned.m16n8k16.row.col.f32.f16.f16.f32 "
      "{%0,%1,%2,%3}, {%4,%5,%6,%7}, {%8,%9}, {%0,%1,%2,%3};"
      : "+f"(c[0]), "+f"(c[1]), "+f"(c[2]), "+f"(c[3])
      : "r"(a[0]), "r"(a[1]), "r"(a[2]), "r"(a[3]), "r"(b0), "r"(b1));
}
#define LDMX4(r0, r1, r2, r3, addr)                                        \
  asm volatile("ldmatrix.sync.aligned.m8n8.x4.shared.b16 {%0,%1,%2,%3}, [%4];" \
               : "=r"(r0), "=r"(r1), "=r"(r2), "=r"(r3) : "r"(addr))
#define STMX4T(addr, r0, r1, r2, r3)                                       \
  asm volatile("stmatrix.sync.aligned.m8n8.x4.trans.shared.b16 [%0], {%1,%2,%3,%4};" \
               :: "r"(addr), "r"(r0), "r"(r1), "r"(r2), "r"(r3))

// ---------------- K0: bitmap (1 ballot/warp) + u/w + Wv fragments ----------------
#define K0_BYTES 18432
__global__ void __launch_bounds__(512, 2)
gat_prep(const float* __restrict__ Wq, const float* __restrict__ Wk,
         const float* __restrict__ a_src, const float* __restrict__ a_dst,
         const int* __restrict__ gso, const float* __restrict__ Wv) {
  extern __shared__ char sm0[];
  const int tid = threadIdx.x, bx = blockIdx.x;
  const int warp = tid >> 5, lane = tid & 31;

  if (bx < 325) {   // bitmap: 325*16 = 5200 warps, one word each
    const int wId = bx * 16 + warp;
    const int r = wId / 13, wj = wId - r * 13;
    const int j = wj * 32 + lane;
    const int v = (j < 400) ? gso[r * 400 + j] : 0;
    const unsigned m = __ballot_sync(0xffffffffu, v != 0);
    if (lane == 0) g_bm[r * 16 + wj] = m;
    return;
  }
  // block 325: u/w vectors + Wv fragment pre-build
  if (tid < 256) {
    const int part = tid >> 6, h = part & 1, c = tid & 63;
    const float* W = (part < 2) ? Wq : Wk;
    const float* a = (part < 2) ? a_src : a_dst;
    float s = 0.f;
#pragma unroll
    for (int d = 0; d < 32; ++d) s += W[(h * 32 + d) * 64 + c] * a[h * 32 + d];
    g_uw[tid] = s;
  }
  __half* sH = (__half*)sm0;            // [64][72]
  __half* sL = (__half*)(sm0 + 9216);
  for (int i = tid; i < 4096; i += 512) {
    const float w = Wv[i];
    const __half wh = __float2half(w);
    const int d = i >> 6, c = i & 63;
    sH[d * 72 + c] = wh;
    sL[d * 72 + c] = __float2half(w - __half2float(wh));
  }
  __syncthreads();
  if (warp == 0) {
    const int mm = lane >> 3, rr = lane & 7;
    const unsigned base = s2u(sm0) + (unsigned)(rr * 144 + (mm & 1) * 16 + (mm >> 1) * 1152);
#pragma unroll
    for (int kk = 0; kk < 4; ++kk)
#pragma unroll
      for (int ntp = 0; ntp < 4; ++ntp) {
        unsigned bh[4], bl[4];
        LDMX4(bh[0], bh[1], bh[2], bh[3], base + ntp * 2304 + kk * 32);
        LDMX4(bl[0], bl[1], bl[2], bl[3], base + 9216 + ntp * 2304 + kk * 32);
        g_wfh[(kk * 4 + ntp) * 32 + lane] = make_uint4(bh[0], bh[1], bh[2], bh[3]);
        g_wfl[(kk * 4 + ntp) * 32 + lane] = make_uint4(bl[0], bl[1], bl[2], bl[3]);
      }
  }
}

// ---------------- K1: fused stage + attention (2 CTAs/SM) ----------------
// smem: x fp16 [400][72] @0 (57600)  → after GEMM: E@0 (12800) | Bit@12800 (27200)
//                                       | LN@40000 (512) | Scr@40512 (2048)
//       V fp16 [64][400] @57600 (51200); sUW aliases @57600 during staging only
#define OV   57600
#define OBIT 12800
#define OLN  40000
#define OSCR 40512
#define SMF_BYTES 108800

__global__ void __launch_bounds__(512, 2)
gat_main(const float* __restrict__ x, const float* __restrict__ ln_g,
         const float* __restrict__ ln_b, float* __restrict__ out) {
  extern __shared__ char sm[];
  const int tid = threadIdx.x, bt = blockIdx.x;
  const int b = bt >> 5, t_ = bt & 31;

  float* sUW = (float*)(sm + OV);   // staging-only alias of V region
  for (int i = tid; i < 256; i += 512) sUW[i] = g_uw[i];
  __syncthreads();

  // ---- staging: scores -> g_E ; x -> fp16 smem (two 32-col chunks) ----
  if (tid < 400) {
    const int r = tid;
    const float* xb = x + (size_t)b * 819200 + (size_t)t_ * 400 + r;
    float s0 = 0.f, s1 = 0.f, d0 = 0.f, d1 = 0.f;
#pragma unroll
    for (int half = 0; half < 2; ++half) {
      const int c0 = half * 32;
      float xr[32];
#pragma unroll
      for (int c = 0; c < 32; ++c) xr[c] = xb[(size_t)(c0 + c) * 12800];
#pragma unroll
      for (int c = 0; c < 32; ++c) {
        const float xc = xr[c];
        s0 += xc * sUW[c0 + c];       s1 += xc * sUW[64 + c0 + c];
        d0 += xc * sUW[128 + c0 + c]; d1 += xc * sUW[192 + c0 + c];
      }
#pragma unroll
      for (int cb = 0; cb < 32; cb += 8) {
        unsigned hp[4];
#pragma unroll
        for (int q2 = 0; q2 < 4; ++q2)
          hp[q2] = f16pack(xr[cb + 2 * q2 + 1], xr[cb + 2 * q2]);
        *(uint4*)(sm + r * 144 + (c0 + cb) * 2) = make_uint4(hp[0], hp[1], hp[2], hp[3]);
      }
    }
    float* E = g_E + (size_t)bt * 3200;
    E[r]        = __expf(s0);        E[400 + r]  = __expf(s1);
    E[800 + r]  = __expf(0.2f * s0); E[1200 + r] = __expf(0.2f * s1);
    E[1600 + r] = __expf(d0);        E[2000 + r] = __expf(d1);
    E[2400 + r] = __expf(0.2f * d0); E[2800 + r] = __expf(0.2f * d1);
  }
  __syncthreads();

  const int warp = tid >> 5, lane = tid & 31;
  const int mm = lane >> 3, rr = lane & 7;

  // ---- V GEMM: 16 warps, tasks w, w+16; stmatrix straight into V region ----
  for (int task = warp; task < 25; task += 16) {
    const int i0t = task * 16;
    float C[8][4];
#pragma unroll
    for (int nt = 0; nt < 8; ++nt)
#pragma unroll
      for (int q = 0; q < 4; ++q) C[nt][q] = 0.f;

    const unsigned xA = s2u(sm) + (unsigned)((i0t + 8 * (mm & 1) + rr) * 144 + (mm >> 1) * 16);
#pragma unroll
    for (int kk = 0; kk < 4; ++kk) {
      unsigned a[4];
      LDMX4(a[0], a[1], a[2], a[3], xA + kk * 32);
#pragma unroll
      for (int ntp = 0; ntp < 4; ++ntp) {
        const uint4 bh = g_wfh[(kk * 4 + ntp) * 32 + lane];   // warp-invariant, L2-hot
        const uint4 bl = g_wfl[(kk * 4 + ntp) * 32 + lane];
        mma16816(C[2 * ntp], a, bh.x, bh.y);
        mma16816(C[2 * ntp], a, bl.x, bl.y);
        mma16816(C[2 * ntp + 1], a, bh.z, bh.w);
        mma16816(C[2 * ntp + 1], a, bl.z, bl.w);
      }
    }
    const int t8 = lane & 7, ntoff = mm >> 1, rhm = mm & 1;
#pragma unroll
    for (int q = 0; q < 4; ++q) {
      unsigned hv[4];
      hv[0] = f16pack(C[2 * q][1],     C[2 * q][0]);
      hv[1] = f16pack(C[2 * q][3],     C[2 * q][2]);
      hv[2] = f16pack(C[2 * q + 1][1], C[2 * q + 1][0]);
      hv[3] = f16pack(C[2 * q + 1][3], C[2 * q + 1][2]);
      const int ntm = 2 * q + ntoff;
      const unsigned sa = s2u(sm + OV) + (unsigned)((8 * ntm + t8) * 800 + (i0t + 8 * rhm) * 2);
      STMX4T(sa, hv[0], hv[1], hv[2], hv[3]);
    }
  }
  __syncthreads();   // x dead; all V written

  // ---- reload E/bitmap/LN into dead x region ----
  float* sE = (float*)sm;
  unsigned* sBit = (unsigned*)(sm + OBIT);
  float* sLN = (float*)(sm + OLN);
  float* sScr = (float*)(sm + OSCR);
  {
    uint4* e4 = (uint4*)sE;
    const uint4* ge = (const uint4*)(g_E + (size_t)bt * 3200);
    for (int i = tid; i < 800; i += 512) e4[i] = ge[i];
    for (int i = tid; i < 6400; i += 512) sBit[(i >> 4) * 17 + (i & 15)] = g_bm[i];
    for (int i = tid; i < 64; i += 512) { sLN[i] = ln_g[i]; sLN[64 + i] = ln_b[i]; }
  }
  __syncthreads();

  // ---- attention + LN + transposed store (8 pairs x 2 head-warps) ----
  const int g = lane >> 2, tq = lane & 3;
  const int pair = warp >> 1, h = warp & 1;
  float* obase = out + (size_t)b * 819200 + (size_t)t_ * 400;

  for (int t = pair; t < 25; t += 8) {
    const int i0 = t * 16;
    const int r0 = i0 + g, r1 = r0 + 8;
    const float A0 = sE[h * 400 + r0],       A1 = sE[h * 400 + r1];
    const float Q0 = sE[(2 + h) * 400 + r0], Q1 = sE[(2 + h) * 400 + r1];

    float C[4][4];
#pragma unroll
    for (int nt = 0; nt < 4; ++nt)
#pragma unroll
      for (int q = 0; q < 4; ++q) C[nt][q] = 0.f;
    float Cz[4] = {0.f, 0.f, 0.f, 0.f};

    for (int js = 0; js < 25; ++js) {
      const int jb = js * 16;
      const unsigned wd0 = sBit[r0 * 17 + (jb >> 5)];
      const unsigned wd1 = sBit[r1 * 17 + (jb >> 5)];
      const int sh = (jb & 16) + 4 * tq;
      const unsigned n0 = (wd0 >> sh) & 0xFu;
      const unsigned n1 = (wd1 >> sh) & 0xFu;
      unsigned mk[4];
      mk[0] = ((n0 & 1u) ? 0x0000FFFFu : 0u) | ((n0 & 2u) ? 0xFFFF0000u : 0u);
      mk[1] = ((n1 & 1u) ? 0x0000FFFFu : 0u) | ((n1 & 2u) ? 0xFFFF0000u : 0u);
      mk[2] = ((n0 & 4u) ? 0x0000FFFFu : 0u) | ((n0 & 8u) ? 0xFFFF0000u : 0u);
      mk[3] = ((n1 & 4u) ? 0x0000FFFFu : 0u) | ((n1 & 8u) ? 0xFFFF0000u : 0u);
      const int j4 = jb + 4 * tq;

      const float4 Be = *(const float4*)(sE + (4 + h) * 400 + j4);
      const float4 De = *(const float4*)(sE + (6 + h) * 400 + j4);

      // exp(lrelu(si+sj)) = max(Ae*Be, Ce*De)
      const float p00 = fmaxf(A0 * Be.x, Q0 * De.x);
      const float p01 = fmaxf(A0 * Be.y, Q0 * De.y);
      const float p02 = fmaxf(A0 * Be.z, Q0 * De.z);
      const float p03 = fmaxf(A0 * Be.w, Q0 * De.w);
      const float p10 = fmaxf(A1 * Be.x, Q1 * De.x);
      const float p11 = fmaxf(A1 * Be.y, Q1 * De.y);
      const float p12 = fmaxf(A1 * Be.z, Q1 * De.z);
      const float p13 = fmaxf(A1 * Be.w, Q1 * De.w);

      const unsigned h0 = f16pack(p01, p00);
      const unsigned h1 = f16pack(p11, p10);
      const unsigned h2 = f16pack(p03, p02);
      const unsigned h3 = f16pack(p13, p12);
      const float2 f0 = h2f(h0), f1 = h2f(h1), f2 = h2f(h2), f3 = h2f(h3);
      unsigned ah[4], al[4];
      al[0] = f16pack(p01 - f0.y, p00 - f0.x) & mk[0];
      al[1] = f16pack(p11 - f1.y, p10 - f1.x) & mk[1];
      al[2] = f16pack(p03 - f2.y, p02 - f2.x) & mk[2];
      al[3] = f16pack(p13 - f3.y, p12 - f3.x) & mk[3];
      ah[0] = h0 & mk[0]; ah[1] = h1 & mk[1];
      ah[2] = h2 & mk[2]; ah[3] = h3 & mk[3];

      mma16816(Cz, ah, 0x3C003C00u, 0x3C003C00u);
      mma16816(Cz, al, 0x3C003C00u, 0x3C003C00u);

#pragma unroll
      for (int nt = 0; nt < 4; ++nt) {
        const int d = h * 32 + nt * 8 + g;
        const ull bv = *(const ull*)(sm + OV + d * 800 + 2 * j4);
        mma16816(C[nt], ah, (unsigned)bv, (unsigned)(bv >> 32));
        mma16816(C[nt], al, (unsigned)bv, (unsigned)(bv >> 32));
      }
    }

    const float rz0 = 1.f / Cz[0], rz1 = 1.f / Cz[2];
#pragma unroll
    for (int nt = 0; nt < 4; ++nt) {
      C[nt][0] *= rz0; C[nt][1] *= rz0;
      C[nt][2] *= rz1; C[nt][3] *= rz1;
    }

#pragma unroll
    for (int rh = 0; rh < 2; ++rh) {
      float s = 0.f, ss = 0.f;
#pragma unroll
      for (int nt = 0; nt < 4; ++nt) {
        const float o0 = C[nt][rh * 2], o1 = C[nt][rh * 2 + 1];
        s += o0 + o1; ss += o0 * o0 + o1 * o1;
      }
      s  += __shfl_xor_sync(0xffffffffu, s, 1);  s  += __shfl_xor_sync(0xffffffffu, s, 2);
      ss += __shfl_xor_sync(0xffffffffu, ss, 1); ss += __shfl_xor_sync(0xffffffffu, ss, 2);
      if (tq == 0) {
        const int row = g + 8 * rh;
        sScr[((pair * 2 + h) * 16 + row) * 2]     = s;
        sScr[((pair * 2 + h) * 16 + row) * 2 + 1] = ss;
      }
    }
    asm volatile("bar.sync %0, 64;" :: "r"(pair + 1) : "memory");
#pragma unroll
    for (int rh = 0; rh < 2; ++rh) {
      const int row = g + 8 * rh;
      float s = 0.f, ss = 0.f;
#pragma unroll
      for (int nt = 0; nt < 4; ++nt) {
        const float o0 = C[nt][rh * 2], o1 = C[nt][rh * 2 + 1];
        s += o0 + o1; ss += o0 * o0 + o1 * o1;
      }
      s  += __shfl_xor_sync(0xffffffffu, s, 1);  s  += __shfl_xor_sync(0xffffffffu, s, 2);
      ss += __shfl_xor_sync(0xffffffffu, ss, 1); ss += __shfl_xor_sync(0xffffffffu, ss, 2);
      s  += sScr[((pair * 2 + (1 - h)) * 16 + row) * 2];
      ss += sScr[((pair * 2 + (1 - h)) * 16 + row) * 2 + 1];
      const float mu = s * (1.f / 64.f);
      const float var = ss * (1.f / 64.f) - mu * mu;
      const float rs = rsqrtf(var + 1e-5f);
      const int n = i0 + row;
#pragma unroll
      for (int nt = 0; nt < 4; ++nt) {
        const int d0 = h * 32 + nt * 8 + 2 * tq;
        const float o0 = (C[nt][rh * 2] - mu) * rs * sLN[d0] + sLN[64 + d0];
        const float o1 = (C[nt][rh * 2 + 1] - mu) * rs * sLN[d0 + 1] + sLN[64 + d0 + 1];
        obase[(size_t)d0 * 12800 + n] = o0;
        obase[(size_t)(d0 + 1) * 12800 + n] = o1;
      }
    }
    asm volatile("bar.sync %0, 64;" :: "r"(pair + 1) : "memory");
  }
}

extern "C" void kernel_launch(void* const* d_in, const int* in_sizes, int n_in,
                              void* d_out, int out_size) {
  const float* x     = (const float*)d_in[0];
  const float* Wq    = (const float*)d_in[1];
  const float* Wk    = (const float*)d_in[2];
  const float* Wv    = (const float*)d_in[3];
  const float* a_src = (const float*)d_in[4];
  const float* a_dst = (const float*)d_in[5];
  const float* ln_g  = (const float*)d_in[6];
  const float* ln_b  = (const float*)d_in[7];
  const int*   gso   = (const int*)d_in[8];
  float* out = (float*)d_out;

  cudaFuncSetAttribute(gat_prep, cudaFuncAttributeMaxDynamicSharedMemorySize, K0_BYTES);
  cudaFuncSetAttribute(gat_main, cudaFuncAttributeMaxDynamicSharedMemorySize, SMF_BYTES);
  gat_prep<<<326, 512, K0_BYTES>>>(Wq, Wk, a_src, a_dst, gso, Wv);
  gat_main<<<256, 512, SMF_BYTES>>>(x, ln_g, ln_b, out);
}

// round 13
// speedup vs baseline: 1.1322x; 1.1322x over previous
#include <cuda_runtime.h>
#include <cuda_fp16.h>

typedef unsigned long long ull;

// ---------------- device scratch (static) ----------------
__device__ unsigned g_bm[400 * 16];               // gso bitmap [i][word]
__device__ __align__(16) __half g_V[256 * 25600]; // V^T fp16 [graph][64][400]
__device__ __align__(16) float g_E[256 * 3200];   // Ae,Ce,Be,De [graph][8][400]

// ---------------- helpers ----------------
__device__ __forceinline__ unsigned f16pack(float hi, float lo) {
  unsigned r;
  asm("cvt.rn.f16x2.f32 %0, %1, %2;" : "=r"(r) : "f"(hi), "f"(lo));
  return r;
}
__device__ __forceinline__ float2 h2f(unsigned u) {
  __half2 h = *reinterpret_cast<__half2*>(&u);
  return __half22float2(h);   // .x = low half, .y = high half
}
__device__ __forceinline__ unsigned s2u(const void* p) {
  return (unsigned)__cvta_generic_to_shared(p);
}
__device__ __forceinline__ void mma16816(float* c, const unsigned* a, unsigned b0, unsigned b1) {
  asm volatile(
      "mma.sync.aligned.m16n8k16.row.col.f32.f16.f16.f32 "
      "{%0,%1,%2,%3}, {%4,%5,%6,%7}, {%8,%9}, {%0,%1,%2,%3};"
      : "+f"(c[0]), "+f"(c[1]), "+f"(c[2]), "+f"(c[3])
      : "r"(a[0]), "r"(a[1]), "r"(a[2]), "r"(a[3]), "r"(b0), "r"(b1));
}
#define LDMX4(r0, r1, r2, r3, addr)                                        \
  asm volatile("ldmatrix.sync.aligned.m8n8.x4.shared.b16 {%0,%1,%2,%3}, [%4];" \
               : "=r"(r0), "=r"(r1), "=r"(r2), "=r"(r3) : "r"(addr))
#define STMX4T(addr, r0, r1, r2, r3)                                       \
  asm volatile("stmatrix.sync.aligned.m8n8.x4.trans.shared.b16 [%0], {%1,%2,%3,%4};" \
               :: "r"(addr), "r"(r0), "r"(r1), "r"(r2), "r"(r3))

// ---------------- K1: stage (bitmap + scores + V projection via fp16 MMA) ----------------
// smem: x fp16 [400][72] @0 (57600) | WvH [64][72] @57600 (9216) | WvL @66816 | UW @76032
// after GEMM, V fp16 [64][400] overlays @0 (51200)
#define K1_WVH 57600
#define K1_WVL 66816
#define K1_UW  76032
#define K1_BYTES 77056

__global__ void __launch_bounds__(800, 1)
gat_stage(const float* __restrict__ x, const float* __restrict__ Wv,
          const float* __restrict__ Wq, const float* __restrict__ Wk,
          const float* __restrict__ a_src, const float* __restrict__ a_dst,
          const int* __restrict__ gso) {
  extern __shared__ char sm[];
  __half* sWvH = (__half*)(sm + K1_WVH);
  __half* sWvL = (__half*)(sm + K1_WVL);
  float* sUW = (float*)(sm + K1_UW);

  const int tid = threadIdx.x, bt = blockIdx.x;
  const int b = bt >> 5, t_ = bt & 31;
  const int warp = tid >> 5, lane = tid & 31;

  // ---- gso bitmap: one ballot per warp, distributed over the whole grid ----
  {
    const int wId = bt * 25 + warp;          // 6400 warps >= 5200 words
    if (wId < 5200) {
      const int r = wId / 13, wj = wId - r * 13;
      const int j = wj * 32 + lane;
      const int v = (j < 400) ? gso[r * 400 + j] : 0;
      const unsigned m = __ballot_sync(0xffffffffu, v != 0);
      if (lane == 0) g_bm[r * 16 + wj] = m;   // consumed only by gat_attn (next kernel)
    }
  }

  // ---- u/w vectors computed in-CTA (redundant per CTA; L2-hot after wave 1) ----
  if (tid < 256) {
    const int part = tid >> 6, h = part & 1, c = tid & 63;
    const float* W = (part < 2) ? Wq : Wk;
    const float* a = (part < 2) ? a_src : a_dst;
    float s = 0.f;
#pragma unroll
    for (int d = 0; d < 32; ++d) s += W[(h * 32 + d) * 64 + c] * a[h * 32 + d];
    sUW[tid] = s;
  }

  // Wv hi/lo split into smem
  for (int i = tid; i < 4096; i += 800) {
    float w = Wv[i];
    __half wh = __float2half(w);
    int d = i >> 6, c = i & 63;
    sWvH[d * 72 + c] = wh;
    sWvL[d * 72 + c] = __float2half(w - __half2float(wh));
  }
  __syncthreads();

  // staging: thread r owns row r (scores -> g_E, x -> fp16 smem)
  if (tid < 400) {
    const int r = tid;
    const float* xb = x + (size_t)b * 819200 + (size_t)t_ * 400 + r;
    float xr[64];
#pragma unroll
    for (int c = 0; c < 64; ++c) xr[c] = xb[(size_t)c * 12800];

    float s0 = 0.f, s1 = 0.f, d0 = 0.f, d1 = 0.f;
#pragma unroll
    for (int c = 0; c < 64; ++c) {
      float xc = xr[c];
      s0 += xc * sUW[c];       s1 += xc * sUW[64 + c];
      d0 += xc * sUW[128 + c]; d1 += xc * sUW[192 + c];
    }
    float* E = g_E + (size_t)bt * 3200;
    E[r]        = __expf(s0);        E[400 + r]  = __expf(s1);
    E[800 + r]  = __expf(0.2f * s0); E[1200 + r] = __expf(0.2f * s1);
    E[1600 + r] = __expf(d0);        E[2000 + r] = __expf(d1);
    E[2400 + r] = __expf(0.2f * d0); E[2800 + r] = __expf(0.2f * d1);

#pragma unroll
    for (int cb = 0; cb < 64; cb += 8) {
      unsigned hp[4];
#pragma unroll
      for (int q2 = 0; q2 < 4; ++q2)
        hp[q2] = f16pack(xr[cb + 2 * q2 + 1], xr[cb + 2 * q2]);
      *(uint4*)(sm + r * 144 + cb * 2) = make_uint4(hp[0], hp[1], hp[2], hp[3]);
    }
  }
  __syncthreads();

  const int mm = lane >> 3, rr = lane & 7;
  const int i0 = warp * 16;

  // GEMM: V = x(fp16) @ (WvH + WvL)^T ; 25 warps, one 16-row tile each
  float C[8][4];
#pragma unroll
  for (int nt = 0; nt < 8; ++nt)
#pragma unroll
    for (int q = 0; q < 4; ++q) C[nt][q] = 0.f;
  {
    const unsigned xA = s2u(sm) + (unsigned)((i0 + 8 * (mm & 1) + rr) * 144 + (mm >> 1) * 16);
    const unsigned wH = s2u(sm + K1_WVH) + (unsigned)(rr * 144 + (mm & 1) * 16 + (mm >> 1) * 1152);
    const unsigned wL = wH + (unsigned)(K1_WVL - K1_WVH);
#pragma unroll
    for (int kk = 0; kk < 4; ++kk) {
      unsigned a[4];
      LDMX4(a[0], a[1], a[2], a[3], xA + kk * 32);
#pragma unroll
      for (int ntp = 0; ntp < 4; ++ntp) {
        unsigned bh[4], bl[4];
        LDMX4(bh[0], bh[1], bh[2], bh[3], wH + ntp * 2304 + kk * 32);
        LDMX4(bl[0], bl[1], bl[2], bl[3], wL + ntp * 2304 + kk * 32);
        mma16816(C[2 * ntp], a, bh[0], bh[1]);
        mma16816(C[2 * ntp], a, bl[0], bl[1]);
        mma16816(C[2 * ntp + 1], a, bh[2], bh[3]);
        mma16816(C[2 * ntp + 1], a, bl[2], bl[3]);
      }
    }
  }
  __syncthreads();   // all x reads done

  // epilogue: C -> fp16 -> V plane via stmatrix.trans (overlay @0)
  {
    const int t8 = lane & 7;
    const int ntoff = (mm >> 1), rhm = mm & 1;
#pragma unroll
    for (int q = 0; q < 4; ++q) {
      unsigned hv[4];
      hv[0] = f16pack(C[2 * q][1],     C[2 * q][0]);
      hv[1] = f16pack(C[2 * q][3],     C[2 * q][2]);
      hv[2] = f16pack(C[2 * q + 1][1], C[2 * q + 1][0]);
      hv[3] = f16pack(C[2 * q + 1][3], C[2 * q + 1][2]);
      const int ntm = 2 * q + ntoff;
      const unsigned sa = s2u(sm) + (unsigned)((8 * ntm + t8) * 800 + (i0 + 8 * rhm) * 2);
      STMX4T(sa, hv[0], hv[1], hv[2], hv[3]);
    }
  }
  __syncthreads();

  // writeout V to gmem
  uint4* dv = (uint4*)(g_V + (size_t)bt * 25600);
  const uint4* sv = (const uint4*)sm;
  for (int i = tid; i < 3200; i += 800) dv[i] = sv[i];
}

// ---------------- K2: attention + LN (2 CTAs/SM) ----------------
// smem: V fp16 [64][400] @0 (51200) | E @51200 (12800) | Bit @64000 (27200, stride 17)
//       | LN @91200 (512) | pairScr @91712 (2048)
#define K2_E    51200
#define K2_BIT  64000
#define K2_LN   91200
#define K2_SCR  91712
#define K2_BYTES 93760

__global__ void __launch_bounds__(512, 2)
gat_attn(const float* __restrict__ ln_g, const float* __restrict__ ln_b,
         float* __restrict__ out) {
  extern __shared__ char sm[];
  float* sE = (float*)(sm + K2_E);
  unsigned* sBit = (unsigned*)(sm + K2_BIT);
  float* sLN = (float*)(sm + K2_LN);
  float* sScr = (float*)(sm + K2_SCR);

  const int tid = threadIdx.x, bt = blockIdx.x;
  const int b = bt >> 5, t_ = bt & 31;

  {  // prologue
    uint4* v4 = (uint4*)sm;
    const uint4* gv = (const uint4*)(g_V + (size_t)bt * 25600);
    for (int i = tid; i < 3200; i += 512) v4[i] = gv[i];
    uint4* e4 = (uint4*)sE;
    const uint4* ge = (const uint4*)(g_E + (size_t)bt * 3200);
    for (int i = tid; i < 800; i += 512) e4[i] = ge[i];
    for (int i = tid; i < 6400; i += 512) sBit[(i >> 4) * 17 + (i & 15)] = g_bm[i];
    for (int i = tid; i < 64; i += 512) { sLN[i] = ln_g[i]; sLN[64 + i] = ln_b[i]; }
  }
  __syncthreads();

  const int warp = tid >> 5, lane = tid & 31;
  const int g = lane >> 2, tq = lane & 3;
  const int pair = warp >> 1, h = warp & 1;
  float* obase = out + (size_t)b * 819200 + (size_t)t_ * 400;

  for (int t = pair; t < 25; t += 8) {
    const int i0 = t * 16;
    const int r0 = i0 + g, r1 = r0 + 8;
    const float A0 = sE[h * 400 + r0],       A1 = sE[h * 400 + r1];
    const float Q0 = sE[(2 + h) * 400 + r0], Q1 = sE[(2 + h) * 400 + r1];

    float C[4][4];
#pragma unroll
    for (int nt = 0; nt < 4; ++nt)
#pragma unroll
      for (int q = 0; q < 4; ++q) C[nt][q] = 0.f;
    float Cz[4] = {0.f, 0.f, 0.f, 0.f};

    for (int js = 0; js < 25; ++js) {
      const int jb = js * 16;
      const unsigned wd0 = sBit[r0 * 17 + (jb >> 5)];
      const unsigned wd1 = sBit[r1 * 17 + (jb >> 5)];
      const int sh = (jb & 16) + 4 * tq;
      const unsigned n0 = (wd0 >> sh) & 0xFu;
      const unsigned n1 = (wd1 >> sh) & 0xFu;
      unsigned mk[4];
      mk[0] = ((n0 & 1u) ? 0x0000FFFFu : 0u) | ((n0 & 2u) ? 0xFFFF0000u : 0u);
      mk[1] = ((n1 & 1u) ? 0x0000FFFFu : 0u) | ((n1 & 2u) ? 0xFFFF0000u : 0u);
      mk[2] = ((n0 & 4u) ? 0x0000FFFFu : 0u) | ((n0 & 8u) ? 0xFFFF0000u : 0u);
      mk[3] = ((n1 & 4u) ? 0x0000FFFFu : 0u) | ((n1 & 8u) ? 0xFFFF0000u : 0u);
      const int j4 = jb + 4 * tq;

      const float4 Be = *(const float4*)(sE + (4 + h) * 400 + j4);
      const float4 De = *(const float4*)(sE + (6 + h) * 400 + j4);

      // exp(lrelu(si+sj)) = max(Ae*Be, Ce*De)
      const float p00 = fmaxf(A0 * Be.x, Q0 * De.x);
      const float p01 = fmaxf(A0 * Be.y, Q0 * De.y);
      const float p02 = fmaxf(A0 * Be.z, Q0 * De.z);
      const float p03 = fmaxf(A0 * Be.w, Q0 * De.w);
      const float p10 = fmaxf(A1 * Be.x, Q1 * De.x);
      const float p11 = fmaxf(A1 * Be.y, Q1 * De.y);
      const float p12 = fmaxf(A1 * Be.z, Q1 * De.z);
      const float p13 = fmaxf(A1 * Be.w, Q1 * De.w);

      const unsigned h0 = f16pack(p01, p00);
      const unsigned h1 = f16pack(p11, p10);
      const unsigned h2 = f16pack(p03, p02);
      const unsigned h3 = f16pack(p13, p12);
      const float2 f0 = h2f(h0), f1 = h2f(h1), f2 = h2f(h2), f3 = h2f(h3);
      unsigned ah[4], al[4];
      al[0] = f16pack(p01 - f0.y, p00 - f0.x) & mk[0];
      al[1] = f16pack(p11 - f1.y, p10 - f1.x) & mk[1];
      al[2] = f16pack(p03 - f2.y, p02 - f2.x) & mk[2];
      al[3] = f16pack(p13 - f3.y, p12 - f3.x) & mk[3];
      ah[0] = h0 & mk[0]; ah[1] = h1 & mk[1];
      ah[2] = h2 & mk[2]; ah[3] = h3 & mk[3];

      // Z via constant-ones B (fp16 1.0 = 0x3C00)
      mma16816(Cz, ah, 0x3C003C00u, 0x3C003C00u);
      mma16816(Cz, al, 0x3C003C00u, 0x3C003C00u);

#pragma unroll
      for (int nt = 0; nt < 4; ++nt) {
        const int d = h * 32 + nt * 8 + g;
        const ull bv = *(const ull*)(sm + d * 800 + 2 * j4);  // 4 fp16 V (conflict-free)
        mma16816(C[nt], ah, (unsigned)bv, (unsigned)(bv >> 32));
        mma16816(C[nt], al, (unsigned)bv, (unsigned)(bv >> 32));
      }
    }

    // normalize by Z
    const float rz0 = 1.f / Cz[0], rz1 = 1.f / Cz[2];
#pragma unroll
    for (int nt = 0; nt < 4; ++nt) {
      C[nt][0] *= rz0; C[nt][1] *= rz0;
      C[nt][2] *= rz1; C[nt][3] *= rz1;
    }

    // partial LN stats (my 32 channels), exchange with partner warp
#pragma unroll
    for (int rh = 0; rh < 2; ++rh) {
      float s = 0.f, ss = 0.f;
#pragma unroll
      for (int nt = 0; nt < 4; ++nt) {
        float o0 = C[nt][rh * 2], o1 = C[nt][rh * 2 + 1];
        s += o0 + o1; ss += o0 * o0 + o1 * o1;
      }
      s  += __shfl_xor_sync(0xffffffffu, s, 1);  s  += __shfl_xor_sync(0xffffffffu, s, 2);
      ss += __shfl_xor_sync(0xffffffffu, ss, 1); ss += __shfl_xor_sync(0xffffffffu, ss, 2);
      if (tq == 0) {
        const int row = g + 8 * rh;
        sScr[((pair * 2 + h) * 16 + row) * 2]     = s;
        sScr[((pair * 2 + h) * 16 + row) * 2 + 1] = ss;
      }
    }
    asm volatile("bar.sync %0, 64;" :: "r"(pair + 1) : "memory");
#pragma unroll
    for (int rh = 0; rh < 2; ++rh) {
      const int row = g + 8 * rh;
      float s = 0.f, ss = 0.f;
#pragma unroll
      for (int nt = 0; nt < 4; ++nt) {
        float o0 = C[nt][rh * 2], o1 = C[nt][rh * 2 + 1];
        s += o0 + o1; ss += o0 * o0 + o1 * o1;
      }
      s  += __shfl_xor_sync(0xffffffffu, s, 1);  s  += __shfl_xor_sync(0xffffffffu, s, 2);
      ss += __shfl_xor_sync(0xffffffffu, ss, 1); ss += __shfl_xor_sync(0xffffffffu, ss, 2);
      s  += sScr[((pair * 2 + (1 - h)) * 16 + row) * 2];
      ss += sScr[((pair * 2 + (1 - h)) * 16 + row) * 2 + 1];
      const float mu = s * (1.f / 64.f);
      const float var = ss * (1.f / 64.f) - mu * mu;
      const float rs = rsqrtf(var + 1e-5f);
      const int n = i0 + row;
#pragma unroll
      for (int nt = 0; nt < 4; ++nt) {
        const int d0 = h * 32 + nt * 8 + 2 * tq;
        float o0 = (C[nt][rh * 2] - mu) * rs * sLN[d0] + sLN[64 + d0];
        float o1 = (C[nt][rh * 2 + 1] - mu) * rs * sLN[d0 + 1] + sLN[64 + d0 + 1];
        obase[(size_t)d0 * 12800 + n] = o0;
        obase[(size_t)(d0 + 1) * 12800 + n] = o1;
      }
    }
    asm volatile("bar.sync %0, 64;" :: "r"(pair + 1) : "memory");  // protect sScr reuse
  }
}

extern "C" void kernel_launch(void* const* d_in, const int* in_sizes, int n_in,
                              void* d_out, int out_size) {
  const float* x     = (const float*)d_in[0];
  const float* Wq    = (const float*)d_in[1];
  const float* Wk    = (const float*)d_in[2];
  const float* Wv    = (const float*)d_in[3];
  const float* a_src = (const float*)d_in[4];
  const float* a_dst = (const float*)d_in[5];
  const float* ln_g  = (const float*)d_in[6];
  const float* ln_b  = (const float*)d_in[7];
  const int*   gso   = (const int*)d_in[8];
  float* out = (float*)d_out;

  cudaFuncSetAttribute(gat_stage, cudaFuncAttributeMaxDynamicSharedMemorySize, K1_BYTES);
  cudaFuncSetAttribute(gat_attn,  cudaFuncAttributeMaxDynamicSharedMemorySize, K2_BYTES);
  gat_stage<<<256, 800, K1_BYTES>>>(x, Wv, Wq, Wk, a_src, a_dst, gso);
  gat_attn<<<256, 512, K2_BYTES>>>(ln_g, ln_b, out);
}

// round 15
// speedup vs baseline: 1.2034x; 1.0629x over previous
#include <cuda_runtime.h>
#include <cuda_fp16.h>

typedef unsigned long long ull;

// ---------------- device scratch (static) ----------------
__device__ __align__(16) __half g_msk[160000];     // gso as fp16 {0,1}, [i][j] (shared by all graphs)
__device__ __align__(16) __half g_V[256 * 25600];  // V^T fp16 [graph][64][400]
__device__ __align__(16) __half g_E[256 * 3200];   // per graph: Ae[2][400] | Ce[2][400] | EBD[2][100][8]

// ---------------- helpers ----------------
__device__ __forceinline__ unsigned f16pack(float hi, float lo) {
  unsigned r;
  asm("cvt.rn.f16x2.f32 %0, %1, %2;" : "=r"(r) : "f"(hi), "f"(lo));
  return r;
}
__device__ __forceinline__ unsigned s2u(const void* p) {
  return (unsigned)__cvta_generic_to_shared(p);
}
__device__ __forceinline__ unsigned hbcast(const __half* p) {
  return (unsigned)__half_as_ushort(*p) * 0x10001u;   // fp16 scalar -> both halves
}
__device__ __forceinline__ unsigned hmul2u(unsigned a, unsigned b) {
  unsigned r;
  asm("mul.f16x2 %0, %1, %2;" : "=r"(r) : "r"(a), "r"(b));
  return r;
}
__device__ __forceinline__ unsigned hmax2u(unsigned a, unsigned b) {
  unsigned r;
  asm("max.f16x2 %0, %1, %2;" : "=r"(r) : "r"(a), "r"(b));
  return r;
}
__device__ __forceinline__ void mma16816(float* c, const unsigned* a, unsigned b0, unsigned b1) {
  asm volatile(
      "mma.sync.aligned.m16n8k16.row.col.f32.f16.f16.f32 "
      "{%0,%1,%2,%3}, {%4,%5,%6,%7}, {%8,%9}, {%0,%1,%2,%3};"
      : "+f"(c[0]), "+f"(c[1]), "+f"(c[2]), "+f"(c[3])
      : "r"(a[0]), "r"(a[1]), "r"(a[2]), "r"(a[3]), "r"(b0), "r"(b1));
}
#define LDMX4(r0, r1, r2, r3, addr)                                        \
  asm volatile("ldmatrix.sync.aligned.m8n8.x4.shared.b16 {%0,%1,%2,%3}, [%4];" \
               : "=r"(r0), "=r"(r1), "=r"(r2), "=r"(r3) : "r"(addr))
#define STMX4T(addr, r0, r1, r2, r3)                                       \
  asm volatile("stmatrix.sync.aligned.m8n8.x4.trans.shared.b16 [%0], {%1,%2,%3,%4};" \
               :: "r"(addr), "r"(r0), "r"(r1), "r"(r2), "r"(r3))

// ---------------- K1: stage (mask + scores fp16 + V projection via fp16 MMA) ----------------
// smem: x fp16 [400][72] @0 (57600) | WvH [64][72] @57600 (9216) | WvL @66816 | UW @76032
// after GEMM, V fp16 [64][400] overlays @0 (51200)
#define K1_WVH 57600
#define K1_WVL 66816
#define K1_UW  76032
#define K1_BYTES 77056

__global__ void __launch_bounds__(800, 1)
gat_stage(const float* __restrict__ x, const float* __restrict__ Wv,
          const float* __restrict__ Wq, const float* __restrict__ Wk,
          const float* __restrict__ a_src, const float* __restrict__ a_dst,
          const int* __restrict__ gso) {
  extern __shared__ char sm[];
  __half* sWvH = (__half*)(sm + K1_WVH);
  __half* sWvL = (__half*)(sm + K1_WVL);
  float* sUW = (float*)(sm + K1_UW);

  const int tid = threadIdx.x, bt = blockIdx.x;
  const int b = bt >> 5, t_ = bt & 31;
  const int warp = tid >> 5, lane = tid & 31;

  // ---- fp16 mask matrix: 40000 int4-groups over the grid (one per thread) ----
  {
    const int i = bt * 800 + tid;
    if (i < 40000) {
      const int4 gv = ((const int4*)gso)[i];
      const unsigned lo = (gv.x ? 0x3C00u : 0u) | (gv.y ? 0x3C000000u : 0u);
      const unsigned hi = (gv.z ? 0x3C00u : 0u) | (gv.w ? 0x3C000000u : 0u);
      ((ull*)g_msk)[i] = ((ull)hi << 32) | lo;   // consumed only by gat_attn
    }
  }

  // ---- u/w vectors computed in-CTA ----
  if (tid < 256) {
    const int part = tid >> 6, h = part & 1, c = tid & 63;
    const float* W = (part < 2) ? Wq : Wk;
    const float* a = (part < 2) ? a_src : a_dst;
    float s = 0.f;
#pragma unroll
    for (int d = 0; d < 32; ++d) s += W[(h * 32 + d) * 64 + c] * a[h * 32 + d];
    sUW[tid] = s;
  }

  // Wv hi/lo split into smem
  for (int i = tid; i < 4096; i += 800) {
    float w = Wv[i];
    __half wh = __float2half(w);
    int d = i >> 6, c = i & 63;
    sWvH[d * 72 + c] = wh;
    sWvL[d * 72 + c] = __float2half(w - __half2float(wh));
  }
  __syncthreads();

  // staging: thread r owns row r (scores -> g_E fp16, x -> fp16 smem)
  if (tid < 400) {
    const int r = tid;
    const float* xb = x + (size_t)b * 819200 + (size_t)t_ * 400 + r;
    float xr[64];
#pragma unroll
    for (int c = 0; c < 64; ++c) xr[c] = xb[(size_t)c * 12800];

    float s0 = 0.f, s1 = 0.f, d0 = 0.f, d1 = 0.f;
#pragma unroll
    for (int c = 0; c < 64; ++c) {
      float xc = xr[c];
      s0 += xc * sUW[c];       s1 += xc * sUW[64 + c];
      d0 += xc * sUW[128 + c]; d1 += xc * sUW[192 + c];
    }
    __half* E = g_E + (size_t)bt * 3200;
    const int jg = (r >> 2) * 8 + (r & 3);
    E[r]         = __float2half(__expf(s0));          // Ae h0
    E[400 + r]   = __float2half(__expf(s1));          // Ae h1
    E[800 + r]   = __float2half(__expf(0.2f * s0));   // Ce h0
    E[1200 + r]  = __float2half(__expf(0.2f * s1));   // Ce h1
    E[1600 + jg]       = __float2half(__expf(d0));          // Be h0
    E[1600 + jg + 4]   = __float2half(__expf(0.2f * d0));   // De h0
    E[2400 + jg]       = __float2half(__expf(d1));          // Be h1
    E[2400 + jg + 4]   = __float2half(__expf(0.2f * d1));   // De h1

#pragma unroll
    for (int cb = 0; cb < 64; cb += 8) {
      unsigned hp[4];
#pragma unroll
      for (int q2 = 0; q2 < 4; ++q2)
        hp[q2] = f16pack(xr[cb + 2 * q2 + 1], xr[cb + 2 * q2]);
      *(uint4*)(sm + r * 144 + cb * 2) = make_uint4(hp[0], hp[1], hp[2], hp[3]);
    }
  }
  __syncthreads();

  const int mm = lane >> 3, rr = lane & 7;
  const int i0 = warp * 16;

  // GEMM: V = x(fp16) @ (WvH + WvL)^T ; 25 warps, one 16-row tile each
  float C[8][4];
#pragma unroll
  for (int nt = 0; nt < 8; ++nt)
#pragma unroll
    for (int q = 0; q < 4; ++q) C[nt][q] = 0.f;
  {
    const unsigned xA = s2u(sm) + (unsigned)((i0 + 8 * (mm & 1) + rr) * 144 + (mm >> 1) * 16);
    const unsigned wH = s2u(sm + K1_WVH) + (unsigned)(rr * 144 + (mm & 1) * 16 + (mm >> 1) * 1152);
    const unsigned wL = wH + (unsigned)(K1_WVL - K1_WVH);
#pragma unroll
    for (int kk = 0; kk < 4; ++kk) {
      unsigned a[4];
      LDMX4(a[0], a[1], a[2], a[3], xA + kk * 32);
#pragma unroll
      for (int ntp = 0; ntp < 4; ++ntp) {
        unsigned bh[4], bl[4];
        LDMX4(bh[0], bh[1], bh[2], bh[3], wH + ntp * 2304 + kk * 32);
        LDMX4(bl[0], bl[1], bl[2], bl[3], wL + ntp * 2304 + kk * 32);
        mma16816(C[2 * ntp], a, bh[0], bh[1]);
        mma16816(C[2 * ntp], a, bl[0], bl[1]);
        mma16816(C[2 * ntp + 1], a, bh[2], bh[3]);
        mma16816(C[2 * ntp + 1], a, bl[2], bl[3]);
      }
    }
  }
  __syncthreads();   // all x reads done

  // epilogue: C -> fp16 -> V plane via stmatrix.trans (overlay @0)
  {
    const int t8 = lane & 7;
    const int ntoff = (mm >> 1), rhm = mm & 1;
#pragma unroll
    for (int q = 0; q < 4; ++q) {
      unsigned hv[4];
      hv[0] = f16pack(C[2 * q][1],     C[2 * q][0]);
      hv[1] = f16pack(C[2 * q][3],     C[2 * q][2]);
      hv[2] = f16pack(C[2 * q + 1][1], C[2 * q + 1][0]);
      hv[3] = f16pack(C[2 * q + 1][3], C[2 * q + 1][2]);
      const int ntm = 2 * q + ntoff;
      const unsigned sa = s2u(sm) + (unsigned)((8 * ntm + t8) * 800 + (i0 + 8 * rhm) * 2);
      STMX4T(sa, hv[0], hv[1], hv[2], hv[3]);
    }
  }
  __syncthreads();

  // writeout V to gmem
  uint4* dv = (uint4*)(g_V + (size_t)bt * 25600);
  const uint4* sv = (const uint4*)sm;
  for (int i = tid; i < 3200; i += 800) dv[i] = sv[i];
}

// ---------------- K2: attention + LN (2 CTAs/SM, fp16 score path) ----------------
// smem: V fp16 [64][400] @0 (51200) | Ae @51200 (1600) | Ce @52800 (1600)
//       | EBD @54400 (3200) | LN @57600 (512) | pairScr @58112 (2048)
#define K2_EA  51200
#define K2_EC  52800
#define K2_EBD 54400
#define K2_LN  57600
#define K2_SCR 58112
#define K2_BYTES 60160

__global__ void __launch_bounds__(512, 2)
gat_attn(const float* __restrict__ ln_g, const float* __restrict__ ln_b,
         float* __restrict__ out) {
  extern __shared__ char sm[];
  float* sLN = (float*)(sm + K2_LN);
  float* sScr = (float*)(sm + K2_SCR);

  const int tid = threadIdx.x, bt = blockIdx.x;
  const int b = bt >> 5, t_ = bt & 31;

  {  // prologue: V + E (fp16, contiguous) + LN
    uint4* v4 = (uint4*)sm;
    const uint4* gv = (const uint4*)(g_V + (size_t)bt * 25600);
    for (int i = tid; i < 3200; i += 512) v4[i] = gv[i];
    uint4* e4 = (uint4*)(sm + K2_EA);
    const uint4* ge = (const uint4*)(g_E + (size_t)bt * 3200);
    for (int i = tid; i < 400; i += 512) e4[i] = ge[i];
    for (int i = tid; i < 64; i += 512) { sLN[i] = ln_g[i]; sLN[64 + i] = ln_b[i]; }
  }
  __syncthreads();

  const int warp = tid >> 5, lane = tid & 31;
  const int g = lane >> 2, tq = lane & 3;
  const int pair = warp >> 1, h = warp & 1;
  const __half* sAe = (const __half*)(sm + K2_EA);
  const __half* sCe = (const __half*)(sm + K2_EC);
  float* obase = out + (size_t)b * 819200 + (size_t)t_ * 400;

  for (int t = pair; t < 25; t += 8) {
    const int i0 = t * 16;
    const int r0 = i0 + g, r1 = r0 + 8;
    // broadcast fp16 row scalars into both halves
    const unsigned A0 = hbcast(sAe + h * 400 + r0);
    const unsigned A1 = hbcast(sAe + h * 400 + r1);
    const unsigned Q0 = hbcast(sCe + h * 400 + r0);
    const unsigned Q1 = hbcast(sCe + h * 400 + r1);

    float C[4][4];
#pragma unroll
    for (int nt = 0; nt < 4; ++nt)
#pragma unroll
      for (int q = 0; q < 4; ++q) C[nt][q] = 0.f;
    float Cz[4] = {0.f, 0.f, 0.f, 0.f};

    const char* ebd = sm + K2_EBD + h * 1600 + tq * 16;
    const __half* mr0 = g_msk + r0 * 400 + 4 * tq;
    const __half* mr1 = g_msk + r1 * 400 + 4 * tq;

    for (int js = 0; js < 25; ++js) {
      const int j4 = js * 16 + 4 * tq;
      const uint4 E = *(const uint4*)(ebd + js * 64);  // x,y = Be(jA,jB); z,w = De
      const ull mw0 = *(const ull*)(mr0 + js * 16);
      const ull mw1 = *(const ull*)(mr1 + js * 16);

      unsigned ah[4];
      // p = max(Ae*Be, Ce*De), then mask multiply (exact {0,1})
      ah[0] = hmul2u(hmax2u(hmul2u(A0, E.x), hmul2u(Q0, E.z)), (unsigned)mw0);
      ah[1] = hmul2u(hmax2u(hmul2u(A1, E.x), hmul2u(Q1, E.z)), (unsigned)mw1);
      ah[2] = hmul2u(hmax2u(hmul2u(A0, E.y), hmul2u(Q0, E.w)), (unsigned)(mw0 >> 32));
      ah[3] = hmul2u(hmax2u(hmul2u(A1, E.y), hmul2u(Q1, E.w)), (unsigned)(mw1 >> 32));

      // Z via constant-ones B (fp16 1.0 = 0x3C00)
      mma16816(Cz, ah, 0x3C003C00u, 0x3C003C00u);

#pragma unroll
      for (int nt = 0; nt < 4; ++nt) {
        const int d = h * 32 + nt * 8 + g;
        const ull bv = *(const ull*)(sm + d * 800 + 2 * j4);  // 4 fp16 V (conflict-free)
        mma16816(C[nt], ah, (unsigned)bv, (unsigned)(bv >> 32));
      }
    }

    // normalize by Z
    const float rz0 = 1.f / Cz[0], rz1 = 1.f / Cz[2];
#pragma unroll
    for (int nt = 0; nt < 4; ++nt) {
      C[nt][0] *= rz0; C[nt][1] *= rz0;
      C[nt][2] *= rz1; C[nt][3] *= rz1;
    }

    // partial LN stats (my 32 channels), exchange with partner head-warp
#pragma unroll
    for (int rh = 0; rh < 2; ++rh) {
      float s = 0.f, ss = 0.f;
#pragma unroll
      for (int nt = 0; nt < 4; ++nt) {
        float o0 = C[nt][rh * 2], o1 = C[nt][rh * 2 + 1];
        s += o0 + o1; ss += o0 * o0 + o1 * o1;
      }
      s  += __shfl_xor_sync(0xffffffffu, s, 1);  s  += __shfl_xor_sync(0xffffffffu, s, 2);
      ss += __shfl_xor_sync(0xffffffffu, ss, 1); ss += __shfl_xor_sync(0xffffffffu, ss, 2);
      if (tq == 0) {
        const int row = g + 8 * rh;
        sScr[((pair * 2 + h) * 16 + row) * 2]     = s;
        sScr[((pair * 2 + h) * 16 + row) * 2 + 1] = ss;
      }
    }
    asm volatile("bar.sync %0, 64;" :: "r"(pair + 1) : "memory");
#pragma unroll
    for (int rh = 0; rh < 2; ++rh) {
      const int row = g + 8 * rh;
      float s = 0.f, ss = 0.f;
#pragma unroll
      for (int nt = 0; nt < 4; ++nt) {
        float o0 = C[nt][rh * 2], o1 = C[nt][rh * 2 + 1];
        s += o0 + o1; ss += o0 * o0 + o1 * o1;
      }
      s  += __shfl_xor_sync(0xffffffffu, s, 1);  s  += __shfl_xor_sync(0xffffffffu, s, 2);
      ss += __shfl_xor_sync(0xffffffffu, ss, 1); ss += __shfl_xor_sync(0xffffffffu, ss, 2);
      s  += sScr[((pair * 2 + (1 - h)) * 16 + row) * 2];
      ss += sScr[((pair * 2 + (1 - h)) * 16 + row) * 2 + 1];
      const float mu = s * (1.f / 64.f);
      const float var = ss * (1.f / 64.f) - mu * mu;
      const float rs = rsqrtf(var + 1e-5f);
      const int n = i0 + row;
#pragma unroll
      for (int nt = 0; nt < 4; ++nt) {
        const int d0 = h * 32 + nt * 8 + 2 * tq;
        float o0 = (C[nt][rh * 2] - mu) * rs * sLN[d0] + sLN[64 + d0];
        float o1 = (C[nt][rh * 2 + 1] - mu) * rs * sLN[d0 + 1] + sLN[64 + d0 + 1];
        obase[(size_t)d0 * 12800 + n] = o0;
        obase[(size_t)(d0 + 1) * 12800 + n] = o1;
      }
    }
    asm volatile("bar.sync %0, 64;" :: "r"(pair + 1) : "memory");  // protect sScr reuse
  }
}

extern "C" void kernel_launch(void* const* d_in, const int* in_sizes, int n_in,
                              void* d_out, int out_size) {
  const float* x     = (const float*)d_in[0];
  const float* Wq    = (const float*)d_in[1];
  const float* Wk    = (const float*)d_in[2];
  const float* Wv    = (const float*)d_in[3];
  const float* a_src = (const float*)d_in[4];
  const float* a_dst = (const float*)d_in[5];
  const float* ln_g  = (const float*)d_in[6];
  const float* ln_b  = (const float*)d_in[7];
  const int*   gso   = (const int*)d_in[8];
  float* out = (float*)d_out;

  cudaFuncSetAttribute(gat_stage, cudaFuncAttributeMaxDynamicSharedMemorySize, K1_BYTES);
  cudaFuncSetAttribute(gat_attn,  cudaFuncAttributeMaxDynamicSharedMemorySize, K2_BYTES);
  gat_stage<<<256, 800, K1_BYTES>>>(x, Wv, Wq, Wk, a_src, a_dst, gso);
  gat_attn<<<256, 512, K2_BYTES>>>(ln_g, ln_b, out);
}

// round 16
// speedup vs baseline: 1.8051x; 1.5000x over previous
#include <cuda_runtime.h>
#include <cuda_fp16.h>

typedef unsigned long long ull;

// ---------------- device scratch (static) ----------------
__device__ unsigned g_bm[400 * 16];                // gso bitmap [i][word]
__device__ __align__(16) __half g_V[256 * 25600];  // V^T fp16 [graph][64][400]
__device__ __align__(16) __half g_E[256 * 3200];   // per graph: Ae[2][400] | Ce[2][400] | EBD[2][100][8]

// ---------------- helpers ----------------
__device__ __forceinline__ unsigned f16pack(float hi, float lo) {
  unsigned r;
  asm("cvt.rn.f16x2.f32 %0, %1, %2;" : "=r"(r) : "f"(hi), "f"(lo));
  return r;
}
__device__ __forceinline__ unsigned s2u(const void* p) {
  return (unsigned)__cvta_generic_to_shared(p);
}
__device__ __forceinline__ unsigned hbcast(const __half* p) {
  return (unsigned)__half_as_ushort(*p) * 0x10001u;   // fp16 scalar -> both halves
}
__device__ __forceinline__ unsigned hmul2u(unsigned a, unsigned b) {
  unsigned r;
  asm("mul.f16x2 %0, %1, %2;" : "=r"(r) : "r"(a), "r"(b));
  return r;
}
__device__ __forceinline__ unsigned hmax2u(unsigned a, unsigned b) {
  unsigned r;
  asm("max.f16x2 %0, %1, %2;" : "=r"(r) : "r"(a), "r"(b));
  return r;
}
__device__ __forceinline__ void mma16816(float* c, const unsigned* a, unsigned b0, unsigned b1) {
  asm volatile(
      "mma.sync.aligned.m16n8k16.row.col.f32.f16.f16.f32 "
      "{%0,%1,%2,%3}, {%4,%5,%6,%7}, {%8,%9}, {%0,%1,%2,%3};"
      : "+f"(c[0]), "+f"(c[1]), "+f"(c[2]), "+f"(c[3])
      : "r"(a[0]), "r"(a[1]), "r"(a[2]), "r"(a[3]), "r"(b0), "r"(b1));
}
#define LDMX4(r0, r1, r2, r3, addr)                                        \
  asm volatile("ldmatrix.sync.aligned.m8n8.x4.shared.b16 {%0,%1,%2,%3}, [%4];" \
               : "=r"(r0), "=r"(r1), "=r"(r2), "=r"(r3) : "r"(addr))
#define STMX4T(addr, r0, r1, r2, r3)                                       \
  asm volatile("stmatrix.sync.aligned.m8n8.x4.trans.shared.b16 [%0], {%1,%2,%3,%4};" \
               :: "r"(addr), "r"(r0), "r"(r1), "r"(r2), "r"(r3))

// ---------------- K1: stage (bitmap + scores fp16 + V projection via fp16 MMA) ----------------
// smem: x fp16 [400][72] @0 (57600) | WvH [64][72] @57600 (9216) | WvL @66816 | UW @76032
// after GEMM, V fp16 [64][400] overlays @0 (51200)
#define K1_WVH 57600
#define K1_WVL 66816
#define K1_UW  76032
#define K1_BYTES 77056

__global__ void __launch_bounds__(800, 1)
gat_stage(const float* __restrict__ x, const float* __restrict__ Wv,
          const float* __restrict__ Wq, const float* __restrict__ Wk,
          const float* __restrict__ a_src, const float* __restrict__ a_dst,
          const int* __restrict__ gso) {
  extern __shared__ char sm[];
  __half* sWvH = (__half*)(sm + K1_WVH);
  __half* sWvL = (__half*)(sm + K1_WVL);
  float* sUW = (float*)(sm + K1_UW);

  const int tid = threadIdx.x, bt = blockIdx.x;
  const int b = bt >> 5, t_ = bt & 31;
  const int warp = tid >> 5, lane = tid & 31;

  // ---- gso bitmap: one ballot per warp across the grid ----
  {
    const int wId = bt * 25 + warp;          // 6400 warps >= 5200 words
    if (wId < 5200) {
      const int r = wId / 13, wj = wId - r * 13;
      const int j = wj * 32 + lane;
      const int v = (j < 400) ? gso[r * 400 + j] : 0;
      const unsigned m = __ballot_sync(0xffffffffu, v != 0);
      if (lane == 0) g_bm[r * 16 + wj] = m;   // consumed only by gat_attn
    }
  }

  // ---- u/w vectors computed in-CTA ----
  if (tid < 256) {
    const int part = tid >> 6, h = part & 1, c = tid & 63;
    const float* W = (part < 2) ? Wq : Wk;
    const float* a = (part < 2) ? a_src : a_dst;
    float s = 0.f;
#pragma unroll
    for (int d = 0; d < 32; ++d) s += W[(h * 32 + d) * 64 + c] * a[h * 32 + d];
    sUW[tid] = s;
  }

  // Wv hi/lo split into smem
  for (int i = tid; i < 4096; i += 800) {
    float w = Wv[i];
    __half wh = __float2half(w);
    int d = i >> 6, c = i & 63;
    sWvH[d * 72 + c] = wh;
    sWvL[d * 72 + c] = __float2half(w - __half2float(wh));
  }
  __syncthreads();

  // staging: thread r owns row r (scores -> g_E fp16, x -> fp16 smem)
  if (tid < 400) {
    const int r = tid;
    const float* xb = x + (size_t)b * 819200 + (size_t)t_ * 400 + r;
    float xr[64];
#pragma unroll
    for (int c = 0; c < 64; ++c) xr[c] = xb[(size_t)c * 12800];

    float s0 = 0.f, s1 = 0.f, d0 = 0.f, d1 = 0.f;
#pragma unroll
    for (int c = 0; c < 64; ++c) {
      float xc = xr[c];
      s0 += xc * sUW[c];       s1 += xc * sUW[64 + c];
      d0 += xc * sUW[128 + c]; d1 += xc * sUW[192 + c];
    }
    __half* E = g_E + (size_t)bt * 3200;
    const int jg = (r >> 2) * 8 + (r & 3);
    E[r]         = __float2half(__expf(s0));          // Ae h0
    E[400 + r]   = __float2half(__expf(s1));          // Ae h1
    E[800 + r]   = __float2half(__expf(0.2f * s0));   // Ce h0
    E[1200 + r]  = __float2half(__expf(0.2f * s1));   // Ce h1
    E[1600 + jg]       = __float2half(__expf(d0));          // Be h0
    E[1600 + jg + 4]   = __float2half(__expf(0.2f * d0));   // De h0
    E[2400 + jg]       = __float2half(__expf(d1));          // Be h1
    E[2400 + jg + 4]   = __float2half(__expf(0.2f * d1));   // De h1

#pragma unroll
    for (int cb = 0; cb < 64; cb += 8) {
      unsigned hp[4];
#pragma unroll
      for (int q2 = 0; q2 < 4; ++q2)
        hp[q2] = f16pack(xr[cb + 2 * q2 + 1], xr[cb + 2 * q2]);
      *(uint4*)(sm + r * 144 + cb * 2) = make_uint4(hp[0], hp[1], hp[2], hp[3]);
    }
  }
  __syncthreads();

  const int mm = lane >> 3, rr = lane & 7;
  const int i0 = warp * 16;

  // GEMM: V = x(fp16) @ (WvH + WvL)^T ; 25 warps, one 16-row tile each
  float C[8][4];
#pragma unroll
  for (int nt = 0; nt < 8; ++nt)
#pragma unroll
    for (int q = 0; q < 4; ++q) C[nt][q] = 0.f;
  {
    const unsigned xA = s2u(sm) + (unsigned)((i0 + 8 * (mm & 1) + rr) * 144 + (mm >> 1) * 16);
    const unsigned wH = s2u(sm + K1_WVH) + (unsigned)(rr * 144 + (mm & 1) * 16 + (mm >> 1) * 1152);
    const unsigned wL = wH + (unsigned)(K1_WVL - K1_WVH);
#pragma unroll
    for (int kk = 0; kk < 4; ++kk) {
      unsigned a[4];
      LDMX4(a[0], a[1], a[2], a[3], xA + kk * 32);
#pragma unroll
      for (int ntp = 0; ntp < 4; ++ntp) {
        unsigned bh[4], bl[4];
        LDMX4(bh[0], bh[1], bh[2], bh[3], wH + ntp * 2304 + kk * 32);
        LDMX4(bl[0], bl[1], bl[2], bl[3], wL + ntp * 2304 + kk * 32);
        mma16816(C[2 * ntp], a, bh[0], bh[1]);
        mma16816(C[2 * ntp], a, bl[0], bl[1]);
        mma16816(C[2 * ntp + 1], a, bh[2], bh[3]);
        mma16816(C[2 * ntp + 1], a, bl[2], bl[3]);
      }
    }
  }
  __syncthreads();   // all x reads done

  // epilogue: C -> fp16 -> V plane via stmatrix.trans (overlay @0)
  {
    const int t8 = lane & 7;
    const int ntoff = (mm >> 1), rhm = mm & 1;
#pragma unroll
    for (int q = 0; q < 4; ++q) {
      unsigned hv[4];
      hv[0] = f16pack(C[2 * q][1],     C[2 * q][0]);
      hv[1] = f16pack(C[2 * q][3],     C[2 * q][2]);
      hv[2] = f16pack(C[2 * q + 1][1], C[2 * q + 1][0]);
      hv[3] = f16pack(C[2 * q + 1][3], C[2 * q + 1][2]);
      const int ntm = 2 * q + ntoff;
      const unsigned sa = s2u(sm) + (unsigned)((8 * ntm + t8) * 800 + (i0 + 8 * rhm) * 2);
      STMX4T(sa, hv[0], hv[1], hv[2], hv[3]);
    }
  }
  __syncthreads();

  // writeout V to gmem
  uint4* dv = (uint4*)(g_V + (size_t)bt * 25600);
  const uint4* sv = (const uint4*)sm;
  for (int i = tid; i < 3200; i += 800) dv[i] = sv[i];
}

// ---------------- K2: attention + LN (2 CTAs/SM, fp16 + bitmap/LUT masks) ----------------
// smem: V fp16 [64][400] @0 (51200) | Ae @51200 (1600) | Ce @52800 (1600)
//       | EBD @54400 (3200) | Bit @57600 (27200, stride 17) | LUT @84800 (128)
//       | LN @84928 (512) | pairScr @85440 (2048)
#define K2_EA  51200
#define K2_EC  52800
#define K2_EBD 54400
#define K2_BIT 57600
#define K2_LUT 84800
#define K2_LN  84928
#define K2_SCR 85440
#define K2_BYTES 87488

__global__ void __launch_bounds__(512, 2)
gat_attn(const float* __restrict__ ln_g, const float* __restrict__ ln_b,
         float* __restrict__ out) {
  extern __shared__ char sm[];
  unsigned* sBit = (unsigned*)(sm + K2_BIT);
  ull* sLUT = (ull*)(sm + K2_LUT);
  float* sLN = (float*)(sm + K2_LN);
  float* sScr = (float*)(sm + K2_SCR);

  const int tid = threadIdx.x, bt = blockIdx.x;
  const int b = bt >> 5, t_ = bt & 31;

  {  // prologue: V + E + bitmap + LUT + LN
    uint4* v4 = (uint4*)sm;
    const uint4* gv = (const uint4*)(g_V + (size_t)bt * 25600);
    for (int i = tid; i < 3200; i += 512) v4[i] = gv[i];
    uint4* e4 = (uint4*)(sm + K2_EA);
    const uint4* ge = (const uint4*)(g_E + (size_t)bt * 3200);
    for (int i = tid; i < 400; i += 512) e4[i] = ge[i];
    for (int i = tid; i < 6400; i += 512) sBit[(i >> 4) * 17 + (i & 15)] = g_bm[i];
    if (tid < 16) {
      const unsigned lo = ((tid & 1) ? 0x0000FFFFu : 0u) | ((tid & 2) ? 0xFFFF0000u : 0u);
      const unsigned hi = ((tid & 4) ? 0x0000FFFFu : 0u) | ((tid & 8) ? 0xFFFF0000u : 0u);
      sLUT[tid] = ((ull)hi << 32) | lo;
    }
    for (int i = tid; i < 64; i += 512) { sLN[i] = ln_g[i]; sLN[64 + i] = ln_b[i]; }
  }
  __syncthreads();

  const int warp = tid >> 5, lane = tid & 31;
  const int g = lane >> 2, tq = lane & 3;
  const int pair = warp >> 1, h = warp & 1;
  const __half* sAe = (const __half*)(sm + K2_EA);
  const __half* sCe = (const __half*)(sm + K2_EC);
  float* obase = out + (size_t)b * 819200 + (size_t)t_ * 400;

  for (int t = pair; t < 25; t += 8) {
    const int i0 = t * 16;
    const int r0 = i0 + g, r1 = r0 + 8;
    const unsigned A0 = hbcast(sAe + h * 400 + r0);
    const unsigned A1 = hbcast(sAe + h * 400 + r1);
    const unsigned Q0 = hbcast(sCe + h * 400 + r0);
    const unsigned Q1 = hbcast(sCe + h * 400 + r1);

    float C[4][4];
#pragma unroll
    for (int nt = 0; nt < 4; ++nt)
#pragma unroll
      for (int q = 0; q < 4; ++q) C[nt][q] = 0.f;
    float Cz[4] = {0.f, 0.f, 0.f, 0.f};

    const char* ebd = sm + K2_EBD + h * 1600 + tq * 16;

#pragma unroll 5
    for (int js = 0; js < 25; ++js) {
      const int jb = js * 16;
      const unsigned wd0 = sBit[r0 * 17 + (jb >> 5)];
      const unsigned wd1 = sBit[r1 * 17 + (jb >> 5)];
      const int sh = (jb & 16) + 4 * tq;
      const ull mk0 = sLUT[(wd0 >> sh) & 0xFu];   // lo: pair(j0,j1); hi: pair(j2,j3)
      const ull mk1 = sLUT[(wd1 >> sh) & 0xFu];
      const int j4 = jb + 4 * tq;
      const uint4 E = *(const uint4*)(ebd + js * 64);  // x,y = Be(jA,jB); z,w = De

      unsigned ah[4];
      // p = max(Ae*Be, Ce*De), then AND-mask (exact +0.0 for masked)
      ah[0] = hmax2u(hmul2u(A0, E.x), hmul2u(Q0, E.z)) & (unsigned)mk0;
      ah[1] = hmax2u(hmul2u(A1, E.x), hmul2u(Q1, E.z)) & (unsigned)mk1;
      ah[2] = hmax2u(hmul2u(A0, E.y), hmul2u(Q0, E.w)) & (unsigned)(mk0 >> 32);
      ah[3] = hmax2u(hmul2u(A1, E.y), hmul2u(Q1, E.w)) & (unsigned)(mk1 >> 32);

      // Z via constant-ones B (fp16 1.0 = 0x3C00)
      mma16816(Cz, ah, 0x3C003C00u, 0x3C003C00u);

#pragma unroll
      for (int nt = 0; nt < 4; ++nt) {
        const int d = h * 32 + nt * 8 + g;
        const ull bv = *(const ull*)(sm + d * 800 + 2 * j4);  // 4 fp16 V (conflict-free)
        mma16816(C[nt], ah, (unsigned)bv, (unsigned)(bv >> 32));
      }
    }

    // normalize by Z
    const float rz0 = 1.f / Cz[0], rz1 = 1.f / Cz[2];
#pragma unroll
    for (int nt = 0; nt < 4; ++nt) {
      C[nt][0] *= rz0; C[nt][1] *= rz0;
      C[nt][2] *= rz1; C[nt][3] *= rz1;
    }

    // partial LN stats (my 32 channels), exchange with partner head-warp
#pragma unroll
    for (int rh = 0; rh < 2; ++rh) {
      float s = 0.f, ss = 0.f;
#pragma unroll
      for (int nt = 0; nt < 4; ++nt) {
        float o0 = C[nt][rh * 2], o1 = C[nt][rh * 2 + 1];
        s += o0 + o1; ss += o0 * o0 + o1 * o1;
      }
      s  += __shfl_xor_sync(0xffffffffu, s, 1);  s  += __shfl_xor_sync(0xffffffffu, s, 2);
      ss += __shfl_xor_sync(0xffffffffu, ss, 1); ss += __shfl_xor_sync(0xffffffffu, ss, 2);
      if (tq == 0) {
        const int row = g + 8 * rh;
        sScr[((pair * 2 + h) * 16 + row) * 2]     = s;
        sScr[((pair * 2 + h) * 16 + row) * 2 + 1] = ss;
      }
    }
    asm volatile("bar.sync %0, 64;" :: "r"(pair + 1) : "memory");
#pragma unroll
    for (int rh = 0; rh < 2; ++rh) {
      const int row = g + 8 * rh;
      float s = 0.f, ss = 0.f;
#pragma unroll
      for (int nt = 0; nt < 4; ++nt) {
        float o0 = C[nt][rh * 2], o1 = C[nt][rh * 2 + 1];
        s += o0 + o1; ss += o0 * o0 + o1 * o1;
      }
      s  += __shfl_xor_sync(0xffffffffu, s, 1);  s  += __shfl_xor_sync(0xffffffffu, s, 2);
      ss += __shfl_xor_sync(0xffffffffu, ss, 1); ss += __shfl_xor_sync(0xffffffffu, ss, 2);
      s  += sScr[((pair * 2 + (1 - h)) * 16 + row) * 2];
      ss += sScr[((pair * 2 + (1 - h)) * 16 + row) * 2 + 1];
      const float mu = s * (1.f / 64.f);
      const float var = ss * (1.f / 64.f) - mu * mu;
      const float rs = rsqrtf(var + 1e-5f);
      const int n = i0 + row;
#pragma unroll
      for (int nt = 0; nt < 4; ++nt) {
        const int d0 = h * 32 + nt * 8 + 2 * tq;
        float o0 = (C[nt][rh * 2] - mu) * rs * sLN[d0] + sLN[64 + d0];
        float o1 = (C[nt][rh * 2 + 1] - mu) * rs * sLN[d0 + 1] + sLN[64 + d0 + 1];
        obase[(size_t)d0 * 12800 + n] = o0;
        obase[(size_t)(d0 + 1) * 12800 + n] = o1;
      }
    }
    asm volatile("bar.sync %0, 64;" :: "r"(pair + 1) : "memory");  // protect sScr reuse
  }
}

extern "C" void kernel_launch(void* const* d_in, const int* in_sizes, int n_in,
                              void* d_out, int out_size) {
  const float* x     = (const float*)d_in[0];
  const float* Wq    = (const float*)d_in[1];
  const float* Wk    = (const float*)d_in[2];
  const float* Wv    = (const float*)d_in[3];
  const float* a_src = (const float*)d_in[4];
  const float* a_dst = (const float*)d_in[5];
  const float* ln_g  = (const float*)d_in[6];
  const float* ln_b  = (const float*)d_in[7];
  const int*   gso   = (const int*)d_in[8];
  float* out = (float*)d_out;

  cudaFuncSetAttribute(gat_stage, cudaFuncAttributeMaxDynamicSharedMemorySize, K1_BYTES);
  cudaFuncSetAttribute(gat_attn,  cudaFuncAttributeMaxDynamicSharedMemorySize, K2_BYTES);
  gat_stage<<<256, 800, K1_BYTES>>>(x, Wv, Wq, Wk, a_src, a_dst, gso);
  gat_attn<<<256, 512, K2_BYTES>>>(ln_g, ln_b, out);
}

// round 17
// speedup vs baseline: 1.8342x; 1.0161x over previous
#include <cuda_runtime.h>
#include <cuda_fp16.h>

typedef unsigned long long ull;

// ---------------- device scratch (static) ----------------
__device__ unsigned g_bm[400 * 16];                // gso bitmap [i][word]
__device__ __align__(16) __half g_V[256 * 25600];  // V^T fp16 [graph][64][400]
__device__ __align__(16) __half g_E[256 * 3200];   // per graph: Ae[2][400] | Ce[2][400] | EBD[2][100][8]

// ---------------- helpers ----------------
__device__ __forceinline__ unsigned f16pack(float hi, float lo) {
  unsigned r;
  asm("cvt.rn.f16x2.f32 %0, %1, %2;" : "=r"(r) : "f"(hi), "f"(lo));
  return r;
}
__device__ __forceinline__ unsigned s2u(const void* p) {
  return (unsigned)__cvta_generic_to_shared(p);
}
__device__ __forceinline__ unsigned hbcast(const __half* p) {
  return (unsigned)__half_as_ushort(*p) * 0x10001u;   // fp16 scalar -> both halves
}
__device__ __forceinline__ unsigned hmul2u(unsigned a, unsigned b) {
  unsigned r;
  asm("mul.f16x2 %0, %1, %2;" : "=r"(r) : "r"(a), "r"(b));
  return r;
}
__device__ __forceinline__ unsigned hmax2u(unsigned a, unsigned b) {
  unsigned r;
  asm("max.f16x2 %0, %1, %2;" : "=r"(r) : "r"(a), "r"(b));
  return r;
}
__device__ __forceinline__ void mma16816(float* c, const unsigned* a, unsigned b0, unsigned b1) {
  asm volatile(
      "mma.sync.aligned.m16n8k16.row.col.f32.f16.f16.f32 "
      "{%0,%1,%2,%3}, {%4,%5,%6,%7}, {%8,%9}, {%0,%1,%2,%3};"
      : "+f"(c[0]), "+f"(c[1]), "+f"(c[2]), "+f"(c[3])
      : "r"(a[0]), "r"(a[1]), "r"(a[2]), "r"(a[3]), "r"(b0), "r"(b1));
}
#define LDMX4(r0, r1, r2, r3, addr)                                        \
  asm volatile("ldmatrix.sync.aligned.m8n8.x4.shared.b16 {%0,%1,%2,%3}, [%4];" \
               : "=r"(r0), "=r"(r1), "=r"(r2), "=r"(r3) : "r"(addr))
#define STMX4T(addr, r0, r1, r2, r3)                                       \
  asm volatile("stmatrix.sync.aligned.m8n8.x4.trans.shared.b16 [%0], {%1,%2,%3,%4};" \
               :: "r"(addr), "r"(r0), "r"(r1), "r"(r2), "r"(r3))

// ---------------- K1: stage (bitmap + scores fp16 + V projection via fp16 MMA) ----------------
// smem: x fp16 [400][72] @0 (57600) | WvH [64][72] @57600 (9216) | WvL @66816 | UW @76032
// after GEMM, V fp16 [64][400] overlays @0 (51200)
#define K1_WVH 57600
#define K1_WVL 66816
#define K1_UW  76032
#define K1_BYTES 77056

__global__ void __launch_bounds__(800, 1)
gat_stage(const float* __restrict__ x, const float* __restrict__ Wv,
          const float* __restrict__ Wq, const float* __restrict__ Wk,
          const float* __restrict__ a_src, const float* __restrict__ a_dst,
          const int* __restrict__ gso) {
  extern __shared__ char sm[];
  __half* sWvH = (__half*)(sm + K1_WVH);
  __half* sWvL = (__half*)(sm + K1_WVL);
  float* sUW = (float*)(sm + K1_UW);

  const int tid = threadIdx.x, bt = blockIdx.x;
  const int b = bt >> 5, t_ = bt & 31;
  const int warp = tid >> 5, lane = tid & 31;

  // ---- gso bitmap: one ballot per warp across the grid ----
  {
    const int wId = bt * 25 + warp;          // 6400 warps >= 5200 words
    if (wId < 5200) {
      const int r = wId / 13, wj = wId - r * 13;
      const int j = wj * 32 + lane;
      const int v = (j < 400) ? gso[r * 400 + j] : 0;
      const unsigned m = __ballot_sync(0xffffffffu, v != 0);
      if (lane == 0) g_bm[r * 16 + wj] = m;   // consumed only by gat_attn
    }
  }

  // ---- u/w vectors computed in-CTA ----
  if (tid < 256) {
    const int part = tid >> 6, h = part & 1, c = tid & 63;
    const float* W = (part < 2) ? Wq : Wk;
    const float* a = (part < 2) ? a_src : a_dst;
    float s = 0.f;
#pragma unroll
    for (int d = 0; d < 32; ++d) s += W[(h * 32 + d) * 64 + c] * a[h * 32 + d];
    sUW[tid] = s;
  }

  // Wv hi/lo split into smem
  for (int i = tid; i < 4096; i += 800) {
    float w = Wv[i];
    __half wh = __float2half(w);
    int d = i >> 6, c = i & 63;
    sWvH[d * 72 + c] = wh;
    sWvL[d * 72 + c] = __float2half(w - __half2float(wh));
  }
  __syncthreads();

  // staging: thread r owns row r (scores -> g_E fp16, x -> fp16 smem)
  if (tid < 400) {
    const int r = tid;
    const float* xb = x + (size_t)b * 819200 + (size_t)t_ * 400 + r;
    float xr[64];
#pragma unroll
    for (int c = 0; c < 64; ++c) xr[c] = xb[(size_t)c * 12800];

    float s0 = 0.f, s1 = 0.f, d0 = 0.f, d1 = 0.f;
#pragma unroll
    for (int c = 0; c < 64; ++c) {
      float xc = xr[c];
      s0 += xc * sUW[c];       s1 += xc * sUW[64 + c];
      d0 += xc * sUW[128 + c]; d1 += xc * sUW[192 + c];
    }
    __half* E = g_E + (size_t)bt * 3200;
    const int jg = (r >> 2) * 8 + (r & 3);
    E[r]         = __float2half(__expf(s0));          // Ae h0
    E[400 + r]   = __float2half(__expf(s1));          // Ae h1
    E[800 + r]   = __float2half(__expf(0.2f * s0));   // Ce h0
    E[1200 + r]  = __float2half(__expf(0.2f * s1));   // Ce h1
    E[1600 + jg]       = __float2half(__expf(d0));          // Be h0
    E[1600 + jg + 4]   = __float2half(__expf(0.2f * d0));   // De h0
    E[2400 + jg]       = __float2half(__expf(d1));          // Be h1
    E[2400 + jg + 4]   = __float2half(__expf(0.2f * d1));   // De h1

#pragma unroll
    for (int cb = 0; cb < 64; cb += 8) {
      unsigned hp[4];
#pragma unroll
      for (int q2 = 0; q2 < 4; ++q2)
        hp[q2] = f16pack(xr[cb + 2 * q2 + 1], xr[cb + 2 * q2]);
      *(uint4*)(sm + r * 144 + cb * 2) = make_uint4(hp[0], hp[1], hp[2], hp[3]);
    }
  }
  __syncthreads();

  const int mm = lane >> 3, rr = lane & 7;
  const int i0 = warp * 16;

  // GEMM: V = x(fp16) @ (WvH + WvL)^T ; 25 warps, one 16-row tile each
  float C[8][4];
#pragma unroll
  for (int nt = 0; nt < 8; ++nt)
#pragma unroll
    for (int q = 0; q < 4; ++q) C[nt][q] = 0.f;
  {
    const unsigned xA = s2u(sm) + (unsigned)((i0 + 8 * (mm & 1) + rr) * 144 + (mm >> 1) * 16);
    const unsigned wH = s2u(sm + K1_WVH) + (unsigned)(rr * 144 + (mm & 1) * 16 + (mm >> 1) * 1152);
    const unsigned wL = wH + (unsigned)(K1_WVL - K1_WVH);
#pragma unroll
    for (int kk = 0; kk < 4; ++kk) {
      unsigned a[4];
      LDMX4(a[0], a[1], a[2], a[3], xA + kk * 32);
#pragma unroll
      for (int ntp = 0; ntp < 4; ++ntp) {
        unsigned bh[4], bl[4];
        LDMX4(bh[0], bh[1], bh[2], bh[3], wH + ntp * 2304 + kk * 32);
        LDMX4(bl[0], bl[1], bl[2], bl[3], wL + ntp * 2304 + kk * 32);
        mma16816(C[2 * ntp], a, bh[0], bh[1]);
        mma16816(C[2 * ntp], a, bl[0], bl[1]);
        mma16816(C[2 * ntp + 1], a, bh[2], bh[3]);
        mma16816(C[2 * ntp + 1], a, bl[2], bl[3]);
      }
    }
  }
  __syncthreads();   // all x reads done

  // epilogue: C -> fp16 -> V plane via stmatrix.trans (overlay @0)
  {
    const int t8 = lane & 7;
    const int ntoff = (mm >> 1), rhm = mm & 1;
#pragma unroll
    for (int q = 0; q < 4; ++q) {
      unsigned hv[4];
      hv[0] = f16pack(C[2 * q][1],     C[2 * q][0]);
      hv[1] = f16pack(C[2 * q][3],     C[2 * q][2]);
      hv[2] = f16pack(C[2 * q + 1][1], C[2 * q + 1][0]);
      hv[3] = f16pack(C[2 * q + 1][3], C[2 * q + 1][2]);
      const int ntm = 2 * q + ntoff;
      const unsigned sa = s2u(sm) + (unsigned)((8 * ntm + t8) * 800 + (i0 + 8 * rhm) * 2);
      STMX4T(sa, hv[0], hv[1], hv[2], hv[3]);
    }
  }
  __syncthreads();

  // writeout V to gmem
  uint4* dv = (uint4*)(g_V + (size_t)bt * 25600);
  const uint4* sv = (const uint4*)sm;
  for (int i = tid; i < 3200; i += 800) dv[i] = sv[i];
}

// ---------------- K2: attention + LN (2 CTAs/SM, fp16 + interleaved bitmap/LUT) ----------------
// smem: V fp16 [64][400] @0 (51200) | Ae @51200 (1600) | Ce @52800 (1600)
//       | EBD @54400 (3200) | Bit2 @57600 (20800: [25][8][13] ull) | LUT @78400 (128)
//       | LN @78528 (512) | pairScr @79040 (2048)
#define K2_EA   51200
#define K2_EC   52800
#define K2_EBD  54400
#define K2_BIT2 57600
#define K2_LUT  78400
#define K2_LN   78528
#define K2_SCR  79040
#define K2_BYTES 81088

__global__ void __launch_bounds__(512, 2)
gat_attn(const float* __restrict__ ln_g, const float* __restrict__ ln_b,
         float* __restrict__ out) {
  extern __shared__ char sm[];
  ull* sBit2 = (ull*)(sm + K2_BIT2);
  ull* sLUT = (ull*)(sm + K2_LUT);
  float* sLN = (float*)(sm + K2_LN);
  float* sScr = (float*)(sm + K2_SCR);

  const int tid = threadIdx.x, bt = blockIdx.x;
  const int b = bt >> 5, t_ = bt & 31;

  {  // prologue: V + E + interleaved bitmap + LUT + LN
    uint4* v4 = (uint4*)sm;
    const uint4* gv = (const uint4*)(g_V + (size_t)bt * 25600);
    for (int i = tid; i < 3200; i += 512) v4[i] = gv[i];
    uint4* e4 = (uint4*)(sm + K2_EA);
    const uint4* ge = (const uint4*)(g_E + (size_t)bt * 3200);
    for (int i = tid; i < 400; i += 512) e4[i] = ge[i];
    // Bit2[(t*8+g)*13 + w] = (word(16t+g, w), word(16t+8+g, w))
    for (int i = tid; i < 2600; i += 512) {
      const int t = i / 104;
      const int rem = i - t * 104;
      const int gg = rem / 13, w = rem - gg * 13;
      const unsigned w0 = g_bm[(t * 16 + gg) * 16 + w];
      const unsigned w1 = g_bm[(t * 16 + 8 + gg) * 16 + w];
      sBit2[(t * 8 + gg) * 13 + w] = ((ull)w1 << 32) | w0;
    }
    if (tid < 16) {
      const unsigned lo = ((tid & 1) ? 0x0000FFFFu : 0u) | ((tid & 2) ? 0xFFFF0000u : 0u);
      const unsigned hi = ((tid & 4) ? 0x0000FFFFu : 0u) | ((tid & 8) ? 0xFFFF0000u : 0u);
      sLUT[tid] = ((ull)hi << 32) | lo;
    }
    for (int i = tid; i < 64; i += 512) { sLN[i] = ln_g[i]; sLN[64 + i] = ln_b[i]; }
  }
  __syncthreads();

  const int warp = tid >> 5, lane = tid & 31;
  const int g = lane >> 2, tq = lane & 3;
  const int pair = warp >> 1, h = warp & 1;
  const __half* sAe = (const __half*)(sm + K2_EA);
  const __half* sCe = (const __half*)(sm + K2_EC);
  float* obase = out + (size_t)b * 819200 + (size_t)t_ * 400;

  for (int t = pair; t < 25; t += 8) {
    const int i0 = t * 16;
    const int r0 = i0 + g, r1 = r0 + 8;
    const unsigned A0 = hbcast(sAe + h * 400 + r0);
    const unsigned A1 = hbcast(sAe + h * 400 + r1);
    const unsigned Q0 = hbcast(sCe + h * 400 + r0);
    const unsigned Q1 = hbcast(sCe + h * 400 + r1);

    float C[4][4];
#pragma unroll
    for (int nt = 0; nt < 4; ++nt)
#pragma unroll
      for (int q = 0; q < 4; ++q) C[nt][q] = 0.f;
    float Cz[4] = {0.f, 0.f, 0.f, 0.f};

    const char* ebd = sm + K2_EBD + h * 1600 + tq * 16;
    const ull* myBits = sBit2 + (t * 8 + g) * 13;

#pragma unroll 3
    for (int ws = 0; ws < 13; ++ws) {
      const ull wp = myBits[ws];                   // (word(r0), word(r1))
      const unsigned wd0 = (unsigned)wp, wd1 = (unsigned)(wp >> 32);
      const int nhalf = (ws < 12) ? 2 : 1;         // ws=12 covers only js=24
#pragma unroll
      for (int hh = 0; hh < 2; ++hh) {
        if (hh >= nhalf) break;
        const int js = ws * 2 + hh;
        const int sh = hh * 16 + 4 * tq;
        const ull mk0 = sLUT[(wd0 >> sh) & 0xFu];  // lo: pair(j0,j1); hi: pair(j2,j3)
        const ull mk1 = sLUT[(wd1 >> sh) & 0xFu];
        const int j4 = js * 16 + 4 * tq;
        const uint4 E = *(const uint4*)(ebd + js * 64);  // x,y = Be(jA,jB); z,w = De

        unsigned ah[4];
        // p = max(Ae*Be, Ce*De), then AND-mask (exact +0.0 for masked)
        ah[0] = hmax2u(hmul2u(A0, E.x), hmul2u(Q0, E.z)) & (unsigned)mk0;
        ah[1] = hmax2u(hmul2u(A1, E.x), hmul2u(Q1, E.z)) & (unsigned)mk1;
        ah[2] = hmax2u(hmul2u(A0, E.y), hmul2u(Q0, E.w)) & (unsigned)(mk0 >> 32);
        ah[3] = hmax2u(hmul2u(A1, E.y), hmul2u(Q1, E.w)) & (unsigned)(mk1 >> 32);

        // Z via constant-ones B (fp16 1.0 = 0x3C00)
        mma16816(Cz, ah, 0x3C003C00u, 0x3C003C00u);

#pragma unroll
        for (int nt = 0; nt < 4; ++nt) {
          const int d = h * 32 + nt * 8 + g;
          const ull bv = *(const ull*)(sm + d * 800 + 2 * j4);  // 4 fp16 V (conflict-free)
          mma16816(C[nt], ah, (unsigned)bv, (unsigned)(bv >> 32));
        }
      }
    }

    // normalize by Z
    const float rz0 = 1.f / Cz[0], rz1 = 1.f / Cz[2];
#pragma unroll
    for (int nt = 0; nt < 4; ++nt) {
      C[nt][0] *= rz0; C[nt][1] *= rz0;
      C[nt][2] *= rz1; C[nt][3] *= rz1;
    }

    // partial LN stats (my 32 channels), exchange with partner head-warp
#pragma unroll
    for (int rh = 0; rh < 2; ++rh) {
      float s = 0.f, ss = 0.f;
#pragma unroll
      for (int nt = 0; nt < 4; ++nt) {
        float o0 = C[nt][rh * 2], o1 = C[nt][rh * 2 + 1];
        s += o0 + o1; ss += o0 * o0 + o1 * o1;
      }
      s  += __shfl_xor_sync(0xffffffffu, s, 1);  s  += __shfl_xor_sync(0xffffffffu, s, 2);
      ss += __shfl_xor_sync(0xffffffffu, ss, 1); ss += __shfl_xor_sync(0xffffffffu, ss, 2);
      if (tq == 0) {
        const int row = g + 8 * rh;
        sScr[((pair * 2 + h) * 16 + row) * 2]     = s;
        sScr[((pair * 2 + h) * 16 + row) * 2 + 1] = ss;
      }
    }
    asm volatile("bar.sync %0, 64;" :: "r"(pair + 1) : "memory");
#pragma unroll
    for (int rh = 0; rh < 2; ++rh) {
      const int row = g + 8 * rh;
      float s = 0.f, ss = 0.f;
#pragma unroll
      for (int nt = 0; nt < 4; ++nt) {
        float o0 = C[nt][rh * 2], o1 = C[nt][rh * 2 + 1];
        s += o0 + o1; ss += o0 * o0 + o1 * o1;
      }
      s  += __shfl_xor_sync(0xffffffffu, s, 1);  s  += __shfl_xor_sync(0xffffffffu, s, 2);
      ss += __shfl_xor_sync(0xffffffffu, ss, 1); ss += __shfl_xor_sync(0xffffffffu, ss, 2);
      s  += sScr[((pair * 2 + (1 - h)) * 16 + row) * 2];
      ss += sScr[((pair * 2 + (1 - h)) * 16 + row) * 2 + 1];
      const float mu = s * (1.f / 64.f);
      const float var = ss * (1.f / 64.f) - mu * mu;
      const float rs = rsqrtf(var + 1e-5f);
      const int n = i0 + row;
#pragma unroll
      for (int nt = 0; nt < 4; ++nt) {
        const int d0 = h * 32 + nt * 8 + 2 * tq;
        float o0 = (C[nt][rh * 2] - mu) * rs * sLN[d0] + sLN[64 + d0];
        float o1 = (C[nt][rh * 2 + 1] - mu) * rs * sLN[d0 + 1] + sLN[64 + d0 + 1];
        obase[(size_t)d0 * 12800 + n] = o0;
        obase[(size_t)(d0 + 1) * 12800 + n] = o1;
      }
    }
    asm volatile("bar.sync %0, 64;" :: "r"(pair + 1) : "memory");  // protect sScr reuse
  }
}

extern "C" void kernel_launch(void* const* d_in, const int* in_sizes, int n_in,
                              void* d_out, int out_size) {
  const float* x     = (const float*)d_in[0];
  const float* Wq    = (const float*)d_in[1];
  const float* Wk    = (const float*)d_in[2];
  const float* Wv    = (const float*)d_in[3];
  const float* a_src = (const float*)d_in[4];
  const float* a_dst = (const float*)d_in[5];
  const float* ln_g  = (const float*)d_in[6];
  const float* ln_b  = (const float*)d_in[7];
  const int*   gso   = (const int*)d_in[8];
  float* out = (float*)d_out;

  cudaFuncSetAttribute(gat_stage, cudaFuncAttributeMaxDynamicSharedMemorySize, K1_BYTES);
  cudaFuncSetAttribute(gat_attn,  cudaFuncAttributeMaxDynamicSharedMemorySize, K2_BYTES);
  gat_stage<<<256, 800, K1_BYTES>>>(x, Wv, Wq, Wk, a_src, a_dst, gso);
  gat_attn<<<256, 512, K2_BYTES>>>(ln_g, ln_b, out);
}